// round 1
// baseline (speedup 1.0000x reference)
#include <cuda_runtime.h>

#define BATCH 8
#define CH    512
#define HW    1024
#define NG    8
#define CPG   64   // channels per group

// -------- scratch (allocation-free: __device__ globals) --------
__device__ float g_h[BATCH*CH*HW];   // groupnorm output
__device__ float g_q[BATCH*CH*HW];
__device__ float g_k[BATCH*CH*HW];
__device__ float g_v[BATCH*CH*HW];
__device__ float g_s[BATCH*HW*HW];   // scores / attn (in place)
__device__ float g_o[BATCH*CH*HW];   // attention output

__inline__ __device__ float warp_sum(float v){
    #pragma unroll
    for (int o = 16; o > 0; o >>= 1) v += __shfl_down_sync(0xffffffffu, v, o);
    return v;
}
__inline__ __device__ float warp_max(float v){
    #pragma unroll
    for (int o = 16; o > 0; o >>= 1) v = fmaxf(v, __shfl_down_sync(0xffffffffu, v, o));
    return v;
}

// ======================= GroupNorm =======================
// grid: 64 blocks (b*8+g), 512 threads
__global__ __launch_bounds__(512) void gn_kernel(const float* __restrict__ x,
                                                 const float* __restrict__ gamma,
                                                 const float* __restrict__ beta){
    int b = blockIdx.x >> 3, g = blockIdx.x & 7;
    size_t base = ((size_t)b*CH + (size_t)g*CPG) * HW;
    const float4* x4 = (const float4*)(x + base);
    float4*       o4 = (float4*)(g_h + base);

    float s = 0.f, ss = 0.f;
    for (int i = threadIdx.x; i < CPG*HW/4; i += 512){
        float4 v = x4[i];
        s  += v.x + v.y + v.z + v.w;
        ss += v.x*v.x + v.y*v.y + v.z*v.z + v.w*v.w;
    }
    __shared__ float r1[16], r2[16];
    int w = threadIdx.x >> 5, l = threadIdx.x & 31;
    s = warp_sum(s); ss = warp_sum(ss);
    if (l == 0){ r1[w] = s; r2[w] = ss; }
    __syncthreads();
    __shared__ float s_mean, s_rstd;
    if (threadIdx.x == 0){
        float S = 0.f, SS = 0.f;
        #pragma unroll
        for (int i = 0; i < 16; i++){ S += r1[i]; SS += r2[i]; }
        float mean = S * (1.f/(CPG*HW));
        float var  = SS * (1.f/(CPG*HW)) - mean*mean;
        s_mean = mean;
        s_rstd = rsqrtf(var + 1e-5f);
    }
    __syncthreads();
    float mean = s_mean, rstd = s_rstd;
    for (int i = threadIdx.x; i < CPG*HW/4; i += 512){
        int ch = g*CPG + (i >> 8);          // 256 float4 per channel
        float sc = gamma[ch]*rstd;
        float bi = beta[ch] - mean*sc;
        float4 v = x4[i];
        v.x = v.x*sc + bi; v.y = v.y*sc + bi;
        v.z = v.z*sc + bi; v.w = v.w*sc + bi;
        o4[i] = v;
    }
}

// ======================= Fused QKV GEMM =======================
// C[o,i] = sum_c W[o,c] * H[b,c,i] + bias[o]
// grid: (16 i-tiles, 24 o-tiles, 8 b), 256 threads, 64x64x16 tiles
__global__ __launch_bounds__(256) void qkv_kernel(const float* __restrict__ wq, const float* __restrict__ bq,
                                                  const float* __restrict__ wk, const float* __restrict__ bk,
                                                  const float* __restrict__ wv, const float* __restrict__ bv){
    int b  = blockIdx.z;
    int i0 = blockIdx.x * 64;
    int o0 = blockIdx.y * 64;
    const float* W; const float* bias; float* out;
    if (o0 < 512)        { W = wq; bias = bq; out = g_q; }
    else if (o0 < 1024)  { o0 -= 512;  W = wk; bias = bk; out = g_k; }
    else                 { o0 -= 1024; W = wv; bias = bv; out = g_v; }
    const float* Hm = g_h + (size_t)b*CH*HW;

    __shared__ float As[16][68];   // [k][m], padded
    __shared__ float Bs[16][64];   // [k][n]
    int tid = threadIdx.x;
    int tx = tid & 15, ty = tid >> 4;
    int rowA = tid >> 2,  colA = (tid & 3)  * 4;
    int rowB = tid >> 4,  colB = (tid & 15) * 4;

    float acc[4][4] = {};
    for (int k0 = 0; k0 < CH; k0 += 16){
        float4 a4 = *(const float4*)(W  + (size_t)(o0+rowA)*CH + k0 + colA);
        float4 b4 = *(const float4*)(Hm + (size_t)(k0+rowB)*HW + i0 + colB);
        As[colA+0][rowA] = a4.x; As[colA+1][rowA] = a4.y;
        As[colA+2][rowA] = a4.z; As[colA+3][rowA] = a4.w;
        *(float4*)&Bs[rowB][colB] = b4;
        __syncthreads();
        #pragma unroll
        for (int k = 0; k < 16; ++k){
            float4 a  = *(const float4*)&As[k][ty*4];
            float4 bb = *(const float4*)&Bs[k][tx*4];
            float av[4] = {a.x, a.y, a.z, a.w};
            float bw[4] = {bb.x, bb.y, bb.z, bb.w};
            #pragma unroll
            for (int i = 0; i < 4; i++)
                #pragma unroll
                for (int j = 0; j < 4; j++)
                    acc[i][j] += av[i]*bw[j];
        }
        __syncthreads();
    }
    #pragma unroll
    for (int i = 0; i < 4; i++){
        int o = o0 + ty*4 + i;
        float bi = bias[o];
        float4 r = make_float4(acc[i][0]+bi, acc[i][1]+bi, acc[i][2]+bi, acc[i][3]+bi);
        *(float4*)(out + ((size_t)b*CH + o)*HW + i0 + tx*4) = r;
    }
}

// ======================= Scores GEMM =======================
// S[i,j] = scale * sum_c Q[c,i]*K[c,j]    (both operands i/j-contiguous)
// grid: (16 j-tiles, 16 i-tiles, 8 b)
__global__ __launch_bounds__(256) void scores_kernel(){
    int b  = blockIdx.z;
    int j0 = blockIdx.x * 64;
    int i0 = blockIdx.y * 64;
    const float* Q = g_q + (size_t)b*CH*HW;
    const float* K = g_k + (size_t)b*CH*HW;

    __shared__ float As[16][64];   // [c][i]
    __shared__ float Bs[16][64];   // [c][j]
    int tid = threadIdx.x;
    int tx = tid & 15, ty = tid >> 4;
    int rowL = tid >> 4, colL = (tid & 15) * 4;

    float acc[4][4] = {};
    for (int k0 = 0; k0 < CH; k0 += 16){
        *(float4*)&As[rowL][colL] = *(const float4*)(Q + (size_t)(k0+rowL)*HW + i0 + colL);
        *(float4*)&Bs[rowL][colL] = *(const float4*)(K + (size_t)(k0+rowL)*HW + j0 + colL);
        __syncthreads();
        #pragma unroll
        for (int k = 0; k < 16; ++k){
            float4 a  = *(const float4*)&As[k][ty*4];
            float4 bb = *(const float4*)&Bs[k][tx*4];
            float av[4] = {a.x, a.y, a.z, a.w};
            float bw[4] = {bb.x, bb.y, bb.z, bb.w};
            #pragma unroll
            for (int i = 0; i < 4; i++)
                #pragma unroll
                for (int j = 0; j < 4; j++)
                    acc[i][j] += av[i]*bw[j];
        }
        __syncthreads();
    }
    const float scale = 0.04419417382415922f;   // 1/sqrt(512)
    #pragma unroll
    for (int i = 0; i < 4; i++){
        float4 r = make_float4(acc[i][0]*scale, acc[i][1]*scale, acc[i][2]*scale, acc[i][3]*scale);
        *(float4*)(g_s + ((size_t)b*HW + i0 + ty*4 + i)*HW + j0 + tx*4) = r;
    }
}

// ======================= Softmax (rows of 1024) =======================
// grid: 8192 blocks, 256 threads; one float4 per thread
__global__ __launch_bounds__(256) void softmax_kernel(){
    size_t row = blockIdx.x;
    float4* s4 = (float4*)(g_s + row*HW);
    float4 v = s4[threadIdx.x];

    __shared__ float red[8];
    __shared__ float s_bcast;
    int w = threadIdx.x >> 5, l = threadIdx.x & 31;

    float m = fmaxf(fmaxf(v.x, v.y), fmaxf(v.z, v.w));
    m = warp_max(m);
    if (l == 0) red[w] = m;
    __syncthreads();
    if (threadIdx.x == 0){
        float M = red[0];
        #pragma unroll
        for (int i = 1; i < 8; i++) M = fmaxf(M, red[i]);
        s_bcast = M;
    }
    __syncthreads();
    float M = s_bcast;
    v.x = __expf(v.x - M); v.y = __expf(v.y - M);
    v.z = __expf(v.z - M); v.w = __expf(v.w - M);
    float s = v.x + v.y + v.z + v.w;
    s = warp_sum(s);
    if (l == 0) red[w] = s;
    __syncthreads();
    if (threadIdx.x == 0){
        float S = 0.f;
        #pragma unroll
        for (int i = 0; i < 8; i++) S += red[i];
        s_bcast = 1.f / S;
    }
    __syncthreads();
    float inv = s_bcast;
    v.x *= inv; v.y *= inv; v.z *= inv; v.w *= inv;
    s4[threadIdx.x] = v;
}

// ======================= Attention output GEMM (NT) =======================
// O[c,i] = sum_j V[c,j] * A[i,j]   (both operands j-contiguous)
// grid: (16 i-tiles, 8 c-tiles, 8 b)
__global__ __launch_bounds__(256) void attnout_kernel(){
    int b  = blockIdx.z;
    int i0 = blockIdx.x * 64;   // n
    int c0 = blockIdx.y * 64;   // m
    const float* V = g_v + (size_t)b*CH*HW;
    const float* A = g_s + (size_t)b*HW*HW;

    __shared__ float As[16][68];   // [j][c]
    __shared__ float Bs[16][68];   // [j][i]
    int tid = threadIdx.x;
    int tx = tid & 15, ty = tid >> 4;
    int rowT = tid >> 2, colT = (tid & 3) * 4;

    float acc[4][4] = {};
    for (int k0 = 0; k0 < HW; k0 += 16){
        float4 a4 = *(const float4*)(V + (size_t)(c0+rowT)*HW + k0 + colT);
        float4 b4 = *(const float4*)(A + (size_t)(i0+rowT)*HW + k0 + colT);
        As[colT+0][rowT] = a4.x; As[colT+1][rowT] = a4.y;
        As[colT+2][rowT] = a4.z; As[colT+3][rowT] = a4.w;
        Bs[colT+0][rowT] = b4.x; Bs[colT+1][rowT] = b4.y;
        Bs[colT+2][rowT] = b4.z; Bs[colT+3][rowT] = b4.w;
        __syncthreads();
        #pragma unroll
        for (int k = 0; k < 16; ++k){
            float4 a  = *(const float4*)&As[k][ty*4];
            float4 bb = *(const float4*)&Bs[k][tx*4];
            float av[4] = {a.x, a.y, a.z, a.w};
            float bw[4] = {bb.x, bb.y, bb.z, bb.w};
            #pragma unroll
            for (int i = 0; i < 4; i++)
                #pragma unroll
                for (int j = 0; j < 4; j++)
                    acc[i][j] += av[i]*bw[j];
        }
        __syncthreads();
    }
    #pragma unroll
    for (int i = 0; i < 4; i++){
        float4 r = make_float4(acc[i][0], acc[i][1], acc[i][2], acc[i][3]);
        *(float4*)(g_o + ((size_t)b*CH + c0 + ty*4 + i)*HW + i0 + tx*4) = r;
    }
}

// ======================= Projection + residual =======================
// out[o,i] = x[b,o,i] + bp[o] + sum_c Wp[o,c]*O[b,c,i]
// grid: (16 i-tiles, 8 o-tiles, 8 b)
__global__ __launch_bounds__(256) void proj_kernel(const float* __restrict__ Wp,
                                                   const float* __restrict__ bp,
                                                   const float* __restrict__ x,
                                                   float* __restrict__ out){
    int b  = blockIdx.z;
    int i0 = blockIdx.x * 64;
    int o0 = blockIdx.y * 64;
    const float* Om = g_o + (size_t)b*CH*HW;

    __shared__ float As[16][68];
    __shared__ float Bs[16][64];
    int tid = threadIdx.x;
    int tx = tid & 15, ty = tid >> 4;
    int rowA = tid >> 2,  colA = (tid & 3)  * 4;
    int rowB = tid >> 4,  colB = (tid & 15) * 4;

    float acc[4][4] = {};
    for (int k0 = 0; k0 < CH; k0 += 16){
        float4 a4 = *(const float4*)(Wp + (size_t)(o0+rowA)*CH + k0 + colA);
        float4 b4 = *(const float4*)(Om + (size_t)(k0+rowB)*HW + i0 + colB);
        As[colA+0][rowA] = a4.x; As[colA+1][rowA] = a4.y;
        As[colA+2][rowA] = a4.z; As[colA+3][rowA] = a4.w;
        *(float4*)&Bs[rowB][colB] = b4;
        __syncthreads();
        #pragma unroll
        for (int k = 0; k < 16; ++k){
            float4 a  = *(const float4*)&As[k][ty*4];
            float4 bb = *(const float4*)&Bs[k][tx*4];
            float av[4] = {a.x, a.y, a.z, a.w};
            float bw[4] = {bb.x, bb.y, bb.z, bb.w};
            #pragma unroll
            for (int i = 0; i < 4; i++)
                #pragma unroll
                for (int j = 0; j < 4; j++)
                    acc[i][j] += av[i]*bw[j];
        }
        __syncthreads();
    }
    #pragma unroll
    for (int i = 0; i < 4; i++){
        int o = o0 + ty*4 + i;
        float bi = bp[o];
        size_t off = ((size_t)b*CH + o)*HW + i0 + tx*4;
        float4 xr = *(const float4*)(x + off);
        float4 r  = make_float4(acc[i][0]+bi+xr.x, acc[i][1]+bi+xr.y,
                                acc[i][2]+bi+xr.z, acc[i][3]+bi+xr.w);
        *(float4*)(out + off) = r;
    }
}

// ======================= launch =======================
extern "C" void kernel_launch(void* const* d_in, const int* in_sizes, int n_in,
                              void* d_out, int out_size){
    const float* x  = (const float*)d_in[0];
    const float* gs = (const float*)d_in[1];
    const float* gb = (const float*)d_in[2];
    const float* wq = (const float*)d_in[3];
    const float* bq = (const float*)d_in[4];
    const float* wk = (const float*)d_in[5];
    const float* bk = (const float*)d_in[6];
    const float* wv = (const float*)d_in[7];
    const float* bv = (const float*)d_in[8];
    const float* wp = (const float*)d_in[9];
    const float* bp = (const float*)d_in[10];
    float* out = (float*)d_out;

    gn_kernel<<<64, 512>>>(x, gs, gb);
    qkv_kernel<<<dim3(16, 24, 8), 256>>>(wq, bq, wk, bk, wv, bv);
    scores_kernel<<<dim3(16, 16, 8), 256>>>();
    softmax_kernel<<<8192, 256>>>();
    attnout_kernel<<<dim3(16, 8, 8), 256>>>();
    proj_kernel<<<dim3(16, 8, 8), 256>>>(wp, bp, x, out);
}

// round 4
// speedup vs baseline: 2.5753x; 2.5753x over previous
#include <cuda_runtime.h>
#include <cstdint>

#define BATCH 8
#define CH    512
#define HW    1024

// ---------------- scratch ----------------
__device__ float g_ht[BATCH*HW*CH];          // groupnorm output, transposed [b][i][c]
__device__ float g_qt[BATCH*HW*CH];          // q transposed [b][i][o]
__device__ float g_kt[BATCH*HW*CH];          // k transposed [b][j][o]
__device__ float g_v [BATCH*CH*HW];          // v [b][c][j]
__device__ float g_s [(size_t)BATCH*HW*HW];  // scores / attn [b][i][j]
__device__ float g_ot[BATCH*HW*CH];          // attn out transposed [b][i][c]
__device__ float g_w [4*CH*CH];              // rna-rounded weights q,k,v,proj
__device__ float g_mean[64];
__device__ float g_rstd[64];

// ---------------- helpers ----------------
__device__ __forceinline__ uint32_t smem_u32(const void* p){
    uint32_t a;
    asm("{ .reg .u64 t; cvta.to.shared.u64 t, %1; cvt.u32.u64 %0, t; }" : "=r"(a) : "l"(p));
    return a;
}
__device__ __forceinline__ void cp16(uint32_t dst, const void* src){
    asm volatile("cp.async.cg.shared.global [%0], [%1], 16;" :: "r"(dst), "l"(src) : "memory");
}
__device__ __forceinline__ void cp_commit(){ asm volatile("cp.async.commit_group;" ::: "memory"); }
template<int N> __device__ __forceinline__ void cp_wait(){
    asm volatile("cp.async.wait_group %0;" :: "n"(N) : "memory");
}
__device__ __forceinline__ float rna_tf32(float x){
    uint32_t u;
    asm("cvt.rna.tf32.f32 %0, %1;" : "=r"(u) : "f"(x));
    return __uint_as_float(u);
}
__device__ __forceinline__ void ldsm4(uint32_t* r, uint32_t addr){
    asm volatile("ldmatrix.sync.aligned.m8n8.x4.shared.b16 {%0,%1,%2,%3}, [%4];"
        : "=r"(r[0]), "=r"(r[1]), "=r"(r[2]), "=r"(r[3]) : "r"(addr));
}
__device__ __forceinline__ void mma8(float* c, const uint32_t a[4], uint32_t b0, uint32_t b1){
    asm volatile("mma.sync.aligned.m16n8k8.row.col.f32.tf32.tf32.f32 "
        "{%0,%1,%2,%3}, {%4,%5,%6,%7}, {%8,%9}, {%0,%1,%2,%3};"
        : "+f"(c[0]), "+f"(c[1]), "+f"(c[2]), "+f"(c[3])
        : "r"(a[0]), "r"(a[1]), "r"(a[2]), "r"(a[3]), "r"(b0), "r"(b1));
}
__inline__ __device__ float warp_sum(float v){
    #pragma unroll
    for (int o = 16; o > 0; o >>= 1) v += __shfl_down_sync(0xffffffffu, v, o);
    return v;
}
__inline__ __device__ float warp_max(float v){
    #pragma unroll
    for (int o = 16; o > 0; o >>= 1) v = fmaxf(v, __shfl_down_sync(0xffffffffu, v, o));
    return v;
}

// ================= GroupNorm stats =================
__global__ __launch_bounds__(256) void gn_stats(const float* __restrict__ x){
    int b = blockIdx.x >> 3, g = blockIdx.x & 7;
    const float4* x4 = (const float4*)(x + ((size_t)b*CH + (size_t)g*64)*HW);
    float s = 0.f, ss = 0.f;
    for (int i = threadIdx.x; i < 64*HW/4; i += 256){
        float4 v = x4[i];
        s  += v.x + v.y + v.z + v.w;
        ss += v.x*v.x + v.y*v.y + v.z*v.z + v.w*v.w;
    }
    __shared__ float r1[8], r2[8];
    int w = threadIdx.x >> 5, l = threadIdx.x & 31;
    s = warp_sum(s); ss = warp_sum(ss);
    if (l == 0){ r1[w] = s; r2[w] = ss; }
    __syncthreads();
    if (threadIdx.x == 0){
        float S = 0.f, SS = 0.f;
        #pragma unroll
        for (int i = 0; i < 8; i++){ S += r1[i]; SS += r2[i]; }
        float mean = S * (1.f/(64.f*HW));
        float var  = SS * (1.f/(64.f*HW)) - mean*mean;
        g_mean[blockIdx.x] = mean;
        g_rstd[blockIdx.x] = rsqrtf(var + 1e-5f);
    }
}

// ============ GroupNorm normalize + transpose (rna-rounded output) ============
__global__ __launch_bounds__(256) void gn_t(const float* __restrict__ x,
                                            const float* __restrict__ gamma,
                                            const float* __restrict__ beta){
    __shared__ float t[32][129];
    int b = blockIdx.z, c0 = blockIdx.y*32, i0 = blockIdx.x*128;
    const float* xb = x + ((size_t)b*CH + c0)*HW + i0;
    for (int idx = threadIdx.x; idx < 32*32; idx += 256){
        int r = idx >> 5, f = idx & 31;
        float4 v = *(const float4*)(xb + (size_t)r*HW + f*4);
        t[r][f*4+0] = v.x; t[r][f*4+1] = v.y; t[r][f*4+2] = v.z; t[r][f*4+3] = v.w;
    }
    __syncthreads();
    float* out = g_ht + ((size_t)b*HW + i0)*CH + c0;
    for (int idx = threadIdx.x; idx < 128*8; idx += 256){
        int i = idx >> 3, cg = idx & 7;
        float o[4];
        #pragma unroll
        for (int e = 0; e < 4; e++){
            int c = cg*4 + e;
            int sidx = b*8 + ((c0 + c) >> 6);
            float sc = gamma[c0+c] * g_rstd[sidx];
            float bi = beta[c0+c] - g_mean[sidx]*sc;
            o[e] = rna_tf32(t[c][i]*sc + bi);
        }
        *(float4*)(out + (size_t)i*CH + cg*4) = make_float4(o[0], o[1], o[2], o[3]);
    }
}

// ============ weight rna-convert ============
__global__ __launch_bounds__(256) void rna_copy4(const float* __restrict__ a, const float* __restrict__ b,
                                                 const float* __restrict__ c, const float* __restrict__ d){
    const float* srcs[4] = {a, b, c, d};
    int z = blockIdx.y;
    const float4* s = (const float4*)srcs[z];
    float4* o = (float4*)(g_w + (size_t)z*CH*CH);
    int i = blockIdx.x*256 + threadIdx.x;      // 256*256 = 65536 float4 = 262144 floats
    float4 v = s[i];
    v.x = rna_tf32(v.x); v.y = rna_tf32(v.y); v.z = rna_tf32(v.z); v.w = rna_tf32(v.w);
    o[i] = v;
}

// ================= mma.sync tf32 GEMM =================
// D[m][n] = scale * sum_k A[m][k]*B[n][k] (+bias_row[m] +bias_col[n] +resid[m][n]) [rna optional]
// CTA 128x128, 8 warps (2x4), warp 64x32, K-chunk 32, 3-stage cp.async, XOR swizzle
#define STAGE_BYTES 32768u
#define MM_SMEM (3*STAGE_BYTES)

__global__ __launch_bounds__(256) void mm_tc(
    const float* __restrict__ A, long long sA, int lda,
    const float* __restrict__ B, long long sB, int ldb,
    float* __restrict__ C, long long sC, int ldc,
    int K,
    const float* __restrict__ bias_row,
    const float* __restrict__ bias_col,
    const float* __restrict__ resid, long long sR,
    float scale, int do_rna)
{
    extern __shared__ float smem[];
    uint32_t sb = smem_u32(smem);
    int tid = threadIdx.x;
    int wid = tid >> 5, lane = tid & 31;
    int wr = wid >> 2, wc = wid & 3;
    int z = blockIdx.z;
    int m0 = blockIdx.y*128, n0 = blockIdx.x*128;
    const float* Ab = A + (long long)z*sA + (size_t)m0*lda;
    const float* Bb = B + (long long)z*sB + (size_t)n0*ldb;

    // fill: each thread covers half a row (4x 16B chunks) of A and of B
    int frow = tid >> 1;
    int fc0  = (tid & 1) * 4;
    uint32_t fdst = (uint32_t)frow * 128u;
    int fx = frow & 7;

    auto FILL = [&](int st, int kc){
        uint32_t base = sb + (uint32_t)st*STAGE_BYTES;
        const float* as = Ab + (size_t)frow*lda + kc*32 + fc0*4;
        const float* bs = Bb + (size_t)frow*ldb + kc*32 + fc0*4;
        #pragma unroll
        for (int j = 0; j < 4; j++){
            uint32_t ph = fdst + (uint32_t)(((fc0 + j) ^ fx) << 4);
            cp16(base + ph, as + j*4);
            cp16(base + 16384u + ph, bs + j*4);
        }
    };

    // ldmatrix lane addressing
    int lrow = lane & 15, lhalf = lane >> 4;
    uint32_t a_off[4]; int a_x[4];
    #pragma unroll
    for (int mt = 0; mt < 4; mt++){
        int r = wr*64 + mt*16 + lrow;
        a_off[mt] = (uint32_t)r*128u; a_x[mt] = r & 7;
    }
    uint32_t b_off[2]; int b_x[2];
    #pragma unroll
    for (int bt = 0; bt < 2; bt++){
        int r = wc*32 + bt*16 + lrow;
        b_off[bt] = (uint32_t)r*128u; b_x[bt] = r & 7;
    }

    float acc[4][4][4] = {};

    auto COMPUTE = [&](int st){
        uint32_t ab = sb + (uint32_t)st*STAGE_BYTES;
        uint32_t bb = ab + 16384u;
        #pragma unroll
        for (int ks = 0; ks < 4; ks++){
            uint32_t afr[4][4], bfr[2][4];
            int cidx = ks*2 + lhalf;
            #pragma unroll
            for (int mt = 0; mt < 4; mt++)
                ldsm4(afr[mt], ab + a_off[mt] + (uint32_t)((cidx ^ a_x[mt]) << 4));
            #pragma unroll
            for (int bt = 0; bt < 2; bt++)
                ldsm4(bfr[bt], bb + b_off[bt] + (uint32_t)((cidx ^ b_x[bt]) << 4));
            #pragma unroll
            for (int mt = 0; mt < 4; mt++){
                #pragma unroll
                for (int bt = 0; bt < 2; bt++){
                    mma8(acc[mt][bt*2+0], afr[mt], bfr[bt][0], bfr[bt][2]);
                    mma8(acc[mt][bt*2+1], afr[mt], bfr[bt][1], bfr[bt][3]);
                }
            }
        }
    };

    int NC = K >> 5;
    FILL(0, 0); cp_commit();
    FILL(1, 1); cp_commit();
    for (int c = 0; c < NC; c++){
        cp_wait<1>();
        __syncthreads();
        if (c + 2 < NC) FILL((c+2)%3, c+2);
        cp_commit();
        COMPUTE(c%3);
    }

    // epilogue
    int g = lane >> 2, t = lane & 3;
    #pragma unroll
    for (int mt = 0; mt < 4; mt++){
        int r1 = m0 + wr*64 + mt*16 + g;
        int r2 = r1 + 8;
        float br1 = bias_row ? __ldg(bias_row + r1) : 0.f;
        float br2 = bias_row ? __ldg(bias_row + r2) : 0.f;
        float* C1 = C + (long long)z*sC + (size_t)r1*ldc;
        float* C2 = C + (long long)z*sC + (size_t)r2*ldc;
        const float* R1 = resid ? resid + (long long)z*sR + (size_t)r1*ldc : nullptr;
        const float* R2 = resid ? resid + (long long)z*sR + (size_t)r2*ldc : nullptr;
        #pragma unroll
        for (int nt = 0; nt < 4; nt++){
            int col = n0 + wc*32 + nt*8 + t*2;
            float v0 = acc[mt][nt][0]*scale + br1;
            float v1 = acc[mt][nt][1]*scale + br1;
            float v2 = acc[mt][nt][2]*scale + br2;
            float v3 = acc[mt][nt][3]*scale + br2;
            if (bias_col){
                float b0 = __ldg(bias_col + col), b1 = __ldg(bias_col + col + 1);
                v0 += b0; v1 += b1; v2 += b0; v3 += b1;
            }
            if (R1){
                v0 += R1[col]; v1 += R1[col+1]; v2 += R2[col]; v3 += R2[col+1];
            }
            if (do_rna){
                v0 = rna_tf32(v0); v1 = rna_tf32(v1); v2 = rna_tf32(v2); v3 = rna_tf32(v3);
            }
            *(float2*)(C1 + col) = make_float2(v0, v1);
            *(float2*)(C2 + col) = make_float2(v2, v3);
        }
    }
}

// ================= Softmax (rows of 1024, rna-rounded output) =================
__global__ __launch_bounds__(256) void softmax_kernel(){
    size_t row = blockIdx.x;
    float4* s4 = (float4*)(g_s + row*HW);
    float4 v = s4[threadIdx.x];

    __shared__ float red[8];
    __shared__ float s_bcast;
    int w = threadIdx.x >> 5, l = threadIdx.x & 31;

    float m = fmaxf(fmaxf(v.x, v.y), fmaxf(v.z, v.w));
    m = warp_max(m);
    if (l == 0) red[w] = m;
    __syncthreads();
    if (threadIdx.x == 0){
        float M = red[0];
        #pragma unroll
        for (int i = 1; i < 8; i++) M = fmaxf(M, red[i]);
        s_bcast = M;
    }
    __syncthreads();
    float M = s_bcast;
    v.x = __expf(v.x - M); v.y = __expf(v.y - M);
    v.z = __expf(v.z - M); v.w = __expf(v.w - M);
    float s = v.x + v.y + v.z + v.w;
    s = warp_sum(s);
    if (l == 0) red[w] = s;
    __syncthreads();
    if (threadIdx.x == 0){
        float S = 0.f;
        #pragma unroll
        for (int i = 0; i < 8; i++) S += red[i];
        s_bcast = 1.f / S;
    }
    __syncthreads();
    float inv = s_bcast;
    v.x = rna_tf32(v.x*inv); v.y = rna_tf32(v.y*inv);
    v.z = rna_tf32(v.z*inv); v.w = rna_tf32(v.w*inv);
    s4[threadIdx.x] = v;
}

// ================= launch =================
extern "C" void kernel_launch(void* const* d_in, const int* in_sizes, int n_in,
                              void* d_out, int out_size){
    const float* x  = (const float*)d_in[0];
    const float* gs = (const float*)d_in[1];
    const float* gb = (const float*)d_in[2];
    const float* wq = (const float*)d_in[3];
    const float* bq = (const float*)d_in[4];
    const float* wk = (const float*)d_in[5];
    const float* bk = (const float*)d_in[6];
    const float* wv = (const float*)d_in[7];
    const float* bv = (const float*)d_in[8];
    const float* wp = (const float*)d_in[9];
    const float* bp = (const float*)d_in[10];
    float* out = (float*)d_out;

    cudaFuncSetAttribute(mm_tc, cudaFuncAttributeMaxDynamicSharedMemorySize, MM_SMEM);

    void *p_ht, *p_qt, *p_kt, *p_v, *p_s, *p_ot, *p_w;
    cudaGetSymbolAddress(&p_ht, g_ht);
    cudaGetSymbolAddress(&p_qt, g_qt);
    cudaGetSymbolAddress(&p_kt, g_kt);
    cudaGetSymbolAddress(&p_v,  g_v);
    cudaGetSymbolAddress(&p_s,  g_s);
    cudaGetSymbolAddress(&p_ot, g_ot);
    cudaGetSymbolAddress(&p_w,  g_w);
    float* ht = (float*)p_ht; float* qt = (float*)p_qt; float* kt = (float*)p_kt;
    float* vv = (float*)p_v;  float* ss = (float*)p_s;  float* ot = (float*)p_ot;
    float* wcq = (float*)p_w;
    float* wck = wcq + (size_t)CH*CH;
    float* wcv = wck + (size_t)CH*CH;
    float* wcp = wcv + (size_t)CH*CH;

    const long long NC_ = (long long)HW*CH;
    const long long SS_ = (long long)HW*HW;
    const float scl = 0.044194173824159216f;  // 1/sqrt(512)

    gn_stats<<<64, 256>>>(x);
    rna_copy4<<<dim3(256, 4), 256>>>(wq, wk, wv, wp);
    gn_t<<<dim3(HW/128, CH/32, BATCH), 256>>>(x, gs, gb);

    // q: D[i][o] = sum_c Ht[i][c]*Wq[o][c] + bq[o]   (rna)
    mm_tc<<<dim3(4, 8, BATCH), 256, MM_SMEM>>>(ht, NC_, CH, wcq, 0, CH,
        qt, NC_, CH, CH, nullptr, bq, nullptr, 0, 1.f, 1);
    // k  (rna)
    mm_tc<<<dim3(4, 8, BATCH), 256, MM_SMEM>>>(ht, NC_, CH, wck, 0, CH,
        kt, NC_, CH, CH, nullptr, bk, nullptr, 0, 1.f, 1);
    // v: D[o][i] = sum_c Wv[o][c]*Ht[i][c] + bv[o]   (rna)
    mm_tc<<<dim3(8, 4, BATCH), 256, MM_SMEM>>>(wcv, 0, CH, ht, NC_, CH,
        vv, NC_, HW, CH, bv, nullptr, nullptr, 0, 1.f, 1);
    // scores: S[i][j] = scl * sum_c Qt[i][c]*Kt[j][c]
    mm_tc<<<dim3(8, 8, BATCH), 256, MM_SMEM>>>(qt, NC_, CH, kt, NC_, CH,
        ss, SS_, HW, CH, nullptr, nullptr, nullptr, 0, scl, 0);
    softmax_kernel<<<BATCH*HW, 256>>>();
    // attnout: Ot[i][c] = sum_j attn[i][j]*V[c][j]   (rna)
    mm_tc<<<dim3(4, 8, BATCH), 256, MM_SMEM>>>(ss, SS_, HW, vv, NC_, HW,
        ot, NC_, CH, HW, nullptr, nullptr, nullptr, 0, 1.f, 1);
    // proj: out[o][i] = sum_c Wp[o][c]*Ot[i][c] + bp[o] + x
    mm_tc<<<dim3(8, 4, BATCH), 256, MM_SMEM>>>(wcp, 0, CH, ot, NC_, CH,
        out, NC_, HW, CH, bp, nullptr, x, NC_, 1.f, 0);
}

// round 5
// speedup vs baseline: 4.3939x; 1.7062x over previous
#include <cuda_runtime.h>
#include <cuda_fp16.h>
#include <cstdint>

#define BATCH 8
#define CH    512
#define HW    1024

// ---------------- scratch ----------------
__device__ __half g_hth[BATCH*HW*CH];         // groupnorm output [b][i][c] fp16
__device__ __half g_qth[BATCH*HW*CH];         // q [b][i][o]
__device__ __half g_kth[BATCH*HW*CH];         // k [b][j][o]
__device__ __half g_vh [BATCH*CH*HW];         // v [b][c][j]
__device__ float  g_s  [(size_t)BATCH*HW*HW]; // scores fp32 [b][i][j]
__device__ __half g_ah [(size_t)BATCH*HW*HW]; // attn fp16 [b][i][j]
__device__ __half g_oth[BATCH*HW*CH];         // attn out [b][i][c]
__device__ __half g_wh [4*CH*CH];             // fp16 weights q,k,v,proj
__device__ float  g_mean[64];
__device__ float  g_rstd[64];

// ---------------- helpers ----------------
__device__ __forceinline__ uint32_t smem_u32(const void* p){
    uint32_t a;
    asm("{ .reg .u64 t; cvta.to.shared.u64 t, %1; cvt.u32.u64 %0, t; }" : "=r"(a) : "l"(p));
    return a;
}
__device__ __forceinline__ void cp16(uint32_t dst, const void* src){
    asm volatile("cp.async.cg.shared.global [%0], [%1], 16;" :: "r"(dst), "l"(src) : "memory");
}
__device__ __forceinline__ void cp_commit(){ asm volatile("cp.async.commit_group;" ::: "memory"); }
template<int N> __device__ __forceinline__ void cp_wait(){
    asm volatile("cp.async.wait_group %0;" :: "n"(N) : "memory");
}
__device__ __forceinline__ void ldsm4(uint32_t* r, uint32_t addr){
    asm volatile("ldmatrix.sync.aligned.m8n8.x4.shared.b16 {%0,%1,%2,%3}, [%4];"
        : "=r"(r[0]), "=r"(r[1]), "=r"(r[2]), "=r"(r[3]) : "r"(addr));
}
__device__ __forceinline__ void mma16(float* c, const uint32_t a[4], uint32_t b0, uint32_t b1){
    asm volatile("mma.sync.aligned.m16n8k16.row.col.f32.f16.f16.f32 "
        "{%0,%1,%2,%3}, {%4,%5,%6,%7}, {%8,%9}, {%0,%1,%2,%3};"
        : "+f"(c[0]), "+f"(c[1]), "+f"(c[2]), "+f"(c[3])
        : "r"(a[0]), "r"(a[1]), "r"(a[2]), "r"(a[3]), "r"(b0), "r"(b1));
}
__inline__ __device__ float warp_sum(float v){
    #pragma unroll
    for (int o = 16; o > 0; o >>= 1) v += __shfl_down_sync(0xffffffffu, v, o);
    return v;
}
__inline__ __device__ float warp_max(float v){
    #pragma unroll
    for (int o = 16; o > 0; o >>= 1) v = fmaxf(v, __shfl_down_sync(0xffffffffu, v, o));
    return v;
}

// ================= GroupNorm stats =================
__global__ __launch_bounds__(256) void gn_stats(const float* __restrict__ x){
    int b = blockIdx.x >> 3, g = blockIdx.x & 7;
    const float4* x4 = (const float4*)(x + ((size_t)b*CH + (size_t)g*64)*HW);
    float s = 0.f, ss = 0.f;
    for (int i = threadIdx.x; i < 64*HW/4; i += 256){
        float4 v = x4[i];
        s  += v.x + v.y + v.z + v.w;
        ss += v.x*v.x + v.y*v.y + v.z*v.z + v.w*v.w;
    }
    __shared__ float r1[8], r2[8];
    int w = threadIdx.x >> 5, l = threadIdx.x & 31;
    s = warp_sum(s); ss = warp_sum(ss);
    if (l == 0){ r1[w] = s; r2[w] = ss; }
    __syncthreads();
    if (threadIdx.x == 0){
        float S = 0.f, SS = 0.f;
        #pragma unroll
        for (int i = 0; i < 8; i++){ S += r1[i]; SS += r2[i]; }
        float mean = S * (1.f/(64.f*HW));
        float var  = SS * (1.f/(64.f*HW)) - mean*mean;
        g_mean[blockIdx.x] = mean;
        g_rstd[blockIdx.x] = rsqrtf(var + 1e-5f);
    }
}

// ============ GroupNorm normalize + transpose -> fp16 ============
__global__ __launch_bounds__(256) void gn_t(const float* __restrict__ x,
                                            const float* __restrict__ gamma,
                                            const float* __restrict__ beta){
    __shared__ float t[32][129];
    int b = blockIdx.z, c0 = blockIdx.y*32, i0 = blockIdx.x*128;
    const float* xb = x + ((size_t)b*CH + c0)*HW + i0;
    for (int idx = threadIdx.x; idx < 32*32; idx += 256){
        int r = idx >> 5, f = idx & 31;
        float4 v = *(const float4*)(xb + (size_t)r*HW + f*4);
        t[r][f*4+0] = v.x; t[r][f*4+1] = v.y; t[r][f*4+2] = v.z; t[r][f*4+3] = v.w;
    }
    __syncthreads();
    __half* out = g_hth + ((size_t)b*HW + i0)*CH + c0;
    for (int idx = threadIdx.x; idx < 128*8; idx += 256){
        int i = idx >> 3, cg = idx & 7;
        float o[4];
        #pragma unroll
        for (int e = 0; e < 4; e++){
            int c = cg*4 + e;
            int sidx = b*8 + ((c0 + c) >> 6);
            float sc = gamma[c0+c] * g_rstd[sidx];
            float bi = beta[c0+c] - g_mean[sidx]*sc;
            o[e] = t[c][i]*sc + bi;
        }
        __half2 h0 = __floats2half2_rn(o[0], o[1]);
        __half2 h1 = __floats2half2_rn(o[2], o[3]);
        *(uint2*)(out + (size_t)i*CH + cg*4) =
            make_uint2(*(uint32_t*)&h0, *(uint32_t*)&h1);
    }
}

// ============ weight fp16 convert ============
__global__ __launch_bounds__(256) void conv_w(const float* __restrict__ a, const float* __restrict__ b,
                                              const float* __restrict__ c, const float* __restrict__ d){
    const float* srcs[4] = {a, b, c, d};
    int z = blockIdx.y;
    const float4* s = (const float4*)srcs[z];
    __half* o = g_wh + (size_t)z*CH*CH;
    int i = blockIdx.x*256 + threadIdx.x;      // 65536 float4
    float4 v = s[i];
    __half2 h0 = __floats2half2_rn(v.x, v.y);
    __half2 h1 = __floats2half2_rn(v.z, v.w);
    *(uint2*)(o + (size_t)i*4) = make_uint2(*(uint32_t*)&h0, *(uint32_t*)&h1);
}

// ================= mma.sync fp16 GEMM =================
// D[m][n] = scale * sum_k A[m][k]*B[n][k] (+bias_row[m] +bias_col[n] +resid[m][n])
// CTA 128x128, 8 warps (2x4), warp 64x32, K-chunk 64 halves (128B rows), 3-stage cp.async
// mode: 0 = f32 output, 1 = fp16 output
#define STAGE_BYTES 32768u
#define MM_SMEM (3*STAGE_BYTES)

__global__ __launch_bounds__(256) void mm_tc(
    const __half* __restrict__ A, long long sA, int lda,
    const __half* __restrict__ B, long long sB, int ldb,
    void* __restrict__ Cv, long long sC, int ldc,
    int K,
    const float* __restrict__ bias_row,
    const float* __restrict__ bias_col,
    const float* __restrict__ resid, long long sR,
    float scale, int mode)
{
    extern __shared__ float smem[];
    uint32_t sb = smem_u32(smem);
    int tid = threadIdx.x;
    int wid = tid >> 5, lane = tid & 31;
    int wr = wid >> 2, wc = wid & 3;
    int z = blockIdx.z;
    int m0 = blockIdx.y*128, n0 = blockIdx.x*128;
    const __half* Ab = A + (long long)z*sA + (size_t)m0*lda;
    const __half* Bb = B + (long long)z*sB + (size_t)n0*ldb;

    // fill: thread covers 4x 16B chunks of one row in A tile and in B tile
    int frow = tid >> 1;
    int fc0  = (tid & 1) * 4;
    uint32_t fdst = (uint32_t)frow * 128u;
    int fx = frow & 7;

    auto FILL = [&](int st, int kc){
        uint32_t base = sb + (uint32_t)st*STAGE_BYTES;
        const __half* as = Ab + (size_t)frow*lda + kc*64 + fc0*8;
        const __half* bs = Bb + (size_t)frow*ldb + kc*64 + fc0*8;
        #pragma unroll
        for (int j = 0; j < 4; j++){
            uint32_t ph = fdst + (uint32_t)(((fc0 + j) ^ fx) << 4);
            cp16(base + ph, as + j*8);
            cp16(base + 16384u + ph, bs + j*8);
        }
    };

    // ldmatrix lane addressing (rows 0-15 by lane&15, chunk parity by lane>>4)
    int lrow = lane & 15, lhalf = lane >> 4;
    uint32_t a_off[4]; int a_x[4];
    #pragma unroll
    for (int mt = 0; mt < 4; mt++){
        int r = wr*64 + mt*16 + lrow;
        a_off[mt] = (uint32_t)r*128u; a_x[mt] = r & 7;
    }
    uint32_t b_off[2]; int b_x[2];
    #pragma unroll
    for (int bt = 0; bt < 2; bt++){
        int r = wc*32 + bt*16 + lrow;
        b_off[bt] = (uint32_t)r*128u; b_x[bt] = r & 7;
    }

    float acc[4][4][4] = {};

    auto COMPUTE = [&](int st){
        uint32_t ab = sb + (uint32_t)st*STAGE_BYTES;
        uint32_t bb = ab + 16384u;
        #pragma unroll
        for (int ks = 0; ks < 4; ks++){          // 4 x k16 = 64 halves
            uint32_t afr[4][4], bfr[2][4];
            int cidx = ks*2 + lhalf;
            #pragma unroll
            for (int mt = 0; mt < 4; mt++)
                ldsm4(afr[mt], ab + a_off[mt] + (uint32_t)((cidx ^ a_x[mt]) << 4));
            #pragma unroll
            for (int bt = 0; bt < 2; bt++)
                ldsm4(bfr[bt], bb + b_off[bt] + (uint32_t)((cidx ^ b_x[bt]) << 4));
            #pragma unroll
            for (int mt = 0; mt < 4; mt++){
                #pragma unroll
                for (int bt = 0; bt < 2; bt++){
                    mma16(acc[mt][bt*2+0], afr[mt], bfr[bt][0], bfr[bt][2]);
                    mma16(acc[mt][bt*2+1], afr[mt], bfr[bt][1], bfr[bt][3]);
                }
            }
        }
    };

    int NC = K >> 6;
    FILL(0, 0); cp_commit();
    FILL(1, 1); cp_commit();
    for (int c = 0; c < NC; c++){
        cp_wait<1>();
        __syncthreads();
        if (c + 2 < NC) FILL((c+2)%3, c+2);
        cp_commit();
        COMPUTE(c%3);
    }

    // epilogue
    int g = lane >> 2, t = lane & 3;
    #pragma unroll
    for (int mt = 0; mt < 4; mt++){
        int r1 = m0 + wr*64 + mt*16 + g;
        int r2 = r1 + 8;
        float br1 = bias_row ? __ldg(bias_row + r1) : 0.f;
        float br2 = bias_row ? __ldg(bias_row + r2) : 0.f;
        #pragma unroll
        for (int nt = 0; nt < 4; nt++){
            int col = n0 + wc*32 + nt*8 + t*2;
            float v0 = acc[mt][nt][0]*scale + br1;
            float v1 = acc[mt][nt][1]*scale + br1;
            float v2 = acc[mt][nt][2]*scale + br2;
            float v3 = acc[mt][nt][3]*scale + br2;
            if (bias_col){
                float b0 = __ldg(bias_col + col), b1 = __ldg(bias_col + col + 1);
                v0 += b0; v1 += b1; v2 += b0; v3 += b1;
            }
            if (mode == 0){
                float* C1 = (float*)Cv + (long long)z*sC + (size_t)r1*ldc;
                float* C2 = (float*)Cv + (long long)z*sC + (size_t)r2*ldc;
                if (resid){
                    const float* R1 = resid + (long long)z*sR + (size_t)r1*ldc;
                    const float* R2 = resid + (long long)z*sR + (size_t)r2*ldc;
                    v0 += R1[col]; v1 += R1[col+1]; v2 += R2[col]; v3 += R2[col+1];
                }
                *(float2*)(C1 + col) = make_float2(v0, v1);
                *(float2*)(C2 + col) = make_float2(v2, v3);
            } else {
                __half* C1 = (__half*)Cv + (long long)z*sC + (size_t)r1*ldc;
                __half* C2 = (__half*)Cv + (long long)z*sC + (size_t)r2*ldc;
                *(__half2*)(C1 + col) = __floats2half2_rn(v0, v1);
                *(__half2*)(C2 + col) = __floats2half2_rn(v2, v3);
            }
        }
    }
}

// ================= Softmax: f32 scores -> fp16 attn =================
__global__ __launch_bounds__(256) void softmax_kernel(){
    size_t row = blockIdx.x;
    const float4* s4 = (const float4*)(g_s + row*HW);
    float4 v = s4[threadIdx.x];

    __shared__ float red[8];
    __shared__ float s_bcast;
    int w = threadIdx.x >> 5, l = threadIdx.x & 31;

    float m = fmaxf(fmaxf(v.x, v.y), fmaxf(v.z, v.w));
    m = warp_max(m);
    if (l == 0) red[w] = m;
    __syncthreads();
    if (threadIdx.x == 0){
        float M = red[0];
        #pragma unroll
        for (int i = 1; i < 8; i++) M = fmaxf(M, red[i]);
        s_bcast = M;
    }
    __syncthreads();
    float M = s_bcast;
    v.x = __expf(v.x - M); v.y = __expf(v.y - M);
    v.z = __expf(v.z - M); v.w = __expf(v.w - M);
    float s = v.x + v.y + v.z + v.w;
    s = warp_sum(s);
    if (l == 0) red[w] = s;
    __syncthreads();
    if (threadIdx.x == 0){
        float S = 0.f;
        #pragma unroll
        for (int i = 0; i < 8; i++) S += red[i];
        s_bcast = 1.f / S;
    }
    __syncthreads();
    float inv = s_bcast;
    __half2 h0 = __floats2half2_rn(v.x*inv, v.y*inv);
    __half2 h1 = __floats2half2_rn(v.z*inv, v.w*inv);
    *(uint2*)(g_ah + row*HW + threadIdx.x*4) =
        make_uint2(*(uint32_t*)&h0, *(uint32_t*)&h1);
}

// ================= launch =================
extern "C" void kernel_launch(void* const* d_in, const int* in_sizes, int n_in,
                              void* d_out, int out_size){
    const float* x  = (const float*)d_in[0];
    const float* gs = (const float*)d_in[1];
    const float* gb = (const float*)d_in[2];
    const float* wq = (const float*)d_in[3];
    const float* bq = (const float*)d_in[4];
    const float* wk = (const float*)d_in[5];
    const float* bk = (const float*)d_in[6];
    const float* wv = (const float*)d_in[7];
    const float* bv = (const float*)d_in[8];
    const float* wp = (const float*)d_in[9];
    const float* bp = (const float*)d_in[10];
    float* out = (float*)d_out;

    cudaFuncSetAttribute(mm_tc, cudaFuncAttributeMaxDynamicSharedMemorySize, MM_SMEM);

    void *p_ht, *p_qt, *p_kt, *p_v, *p_s, *p_a, *p_ot, *p_w;
    cudaGetSymbolAddress(&p_ht, g_hth);
    cudaGetSymbolAddress(&p_qt, g_qth);
    cudaGetSymbolAddress(&p_kt, g_kth);
    cudaGetSymbolAddress(&p_v,  g_vh);
    cudaGetSymbolAddress(&p_s,  g_s);
    cudaGetSymbolAddress(&p_a,  g_ah);
    cudaGetSymbolAddress(&p_ot, g_oth);
    cudaGetSymbolAddress(&p_w,  g_wh);
    __half* ht = (__half*)p_ht; __half* qt = (__half*)p_qt; __half* kt = (__half*)p_kt;
    __half* vv = (__half*)p_v;  float* ss = (float*)p_s;    __half* ah = (__half*)p_a;
    __half* ot = (__half*)p_ot;
    __half* whq = (__half*)p_w;
    __half* whk = whq + (size_t)CH*CH;
    __half* whv = whk + (size_t)CH*CH;
    __half* whp = whv + (size_t)CH*CH;

    const long long NC_ = (long long)HW*CH;
    const long long SS_ = (long long)HW*HW;
    const float scl = 0.044194173824159216f;  // 1/sqrt(512)

    gn_stats<<<64, 256>>>(x);
    conv_w<<<dim3(256, 4), 256>>>(wq, wk, wv, wp);
    gn_t<<<dim3(HW/128, CH/32, BATCH), 256>>>(x, gs, gb);

    // q: D[i][o] = sum_c Ht[i][c]*Wq[o][c] + bq[o]  -> fp16
    mm_tc<<<dim3(4, 8, BATCH), 256, MM_SMEM>>>(ht, NC_, CH, whq, 0, CH,
        qt, NC_, CH, CH, nullptr, bq, nullptr, 0, 1.f, 1);
    // k -> fp16
    mm_tc<<<dim3(4, 8, BATCH), 256, MM_SMEM>>>(ht, NC_, CH, whk, 0, CH,
        kt, NC_, CH, CH, nullptr, bk, nullptr, 0, 1.f, 1);
    // v: D[o][i] = sum_c Wv[o][c]*Ht[i][c] + bv[o]  -> fp16
    mm_tc<<<dim3(8, 4, BATCH), 256, MM_SMEM>>>(whv, 0, CH, ht, NC_, CH,
        vv, NC_, HW, CH, bv, nullptr, nullptr, 0, 1.f, 1);
    // scores: S[i][j] = scl * sum_c Q[i][c]*K[j][c]  -> f32
    mm_tc<<<dim3(8, 8, BATCH), 256, MM_SMEM>>>(qt, NC_, CH, kt, NC_, CH,
        ss, SS_, HW, CH, nullptr, nullptr, nullptr, 0, scl, 0);
    softmax_kernel<<<BATCH*HW, 256>>>();
    // attnout: Ot[i][c] = sum_j attn[i][j]*V[c][j]  -> fp16
    mm_tc<<<dim3(4, 8, BATCH), 256, MM_SMEM>>>(ah, SS_, HW, vv, NC_, HW,
        ot, NC_, CH, HW, nullptr, nullptr, nullptr, 0, 1.f, 1);
    // proj: out[o][i] = sum_c Wp[o][c]*Ot[i][c] + bp[o] + x  -> f32
    mm_tc<<<dim3(8, 4, BATCH), 256, MM_SMEM>>>(whp, 0, CH, ot, NC_, CH,
        out, NC_, HW, CH, bp, nullptr, x, NC_, 1.f, 0);
}